// round 15
// baseline (speedup 1.0000x reference)
#include <cuda_runtime.h>
#include <cuda_bf16.h>
#include <cstdint>

#define B_DIM   64
#define IN_DIM  8192
#define OUT_DIM 8192
#define G_DIM   64
#define NG      (IN_DIM / G_DIM)      // 128 groups per row
#define NCTA    296                   // 148 SMs x 2 CTAs: one perfect wave
#define NUNITS  8192                  // 64 m-tiles x 128 groups
#define NMT     (OUT_DIM / 128)       // 64 m-tiles

// permuted x planes: [g][j(8)][lane(32)][16B]
__device__ __align__(16) uint32_t g_xq1[NG * 8 * 32 * 4];
__device__ __align__(16) uint32_t g_xq2[NG * 8 * 32 * 4];
__device__ int   g_xsums[NG * B_DIM];
__device__ float g_s2[B_DIM];
// per-CTA partials: [cta][slot(2)][row128][b64]
__device__ __align__(16) float g_part2[NCTA * 2 * 128 * B_DIM];
__device__ int g_cnt[NMT];            // arrival counters (self-resetting)
__device__ int g_wfmt;                // 0 = packed u8, 1 = widened i32

__device__ __forceinline__ void mma_s8(int& d0, int& d1, int& d2, int& d3,
                                       uint32_t a0, uint32_t a1, uint32_t a2, uint32_t a3,
                                       uint32_t b0, uint32_t b1,
                                       int c0, int c1, int c2, int c3) {
    asm("mma.sync.aligned.m16n8k32.row.col.s32.s8.s8.s32 "
        "{%0,%1,%2,%3},{%4,%5,%6,%7},{%8,%9},{%10,%11,%12,%13};"
        : "=r"(d0), "=r"(d1), "=r"(d2), "=r"(d3)
        : "r"(a0), "r"(a1), "r"(a2), "r"(a3), "r"(b0), "r"(b1),
          "r"(c0), "r"(c1), "r"(c2), "r"(c3));
}

// ---------------- prep: x quantization + fused weight-format detect ---------
__global__ void __launch_bounds__(256) prep_kernel(const float* __restrict__ x,
                                                   const uint32_t* __restrict__ w) {
    const int b = blockIdx.x;
    const int tid = threadIdx.x;

    if (b == 0) {
        uint32_t acc_w = 0;
#pragma unroll
        for (int i = 0; i < 8; ++i)
            acc_w |= w[(size_t)(tid * 8 + i) * 2048] & 0xFFFFFF00u;
        unsigned any = __syncthreads_or(acc_w != 0u);
        if (tid == 0) g_wfmt = any ? 0 : 1;
    }

    const float* xr = x + (size_t)b * IN_DIM;
    __shared__ float sred[256];
    __shared__ int ssum[256];

    float m = 0.f;
    const float4* xr4 = reinterpret_cast<const float4*>(xr);
#pragma unroll
    for (int it = 0; it < IN_DIM / 4 / 256; ++it) {
        float4 v = xr4[tid + it * 256];
        m = fmaxf(m, fmaxf(fmaxf(fabsf(v.x), fabsf(v.y)), fmaxf(fabsf(v.z), fabsf(v.w))));
    }
    sred[tid] = m;
    __syncthreads();
    for (int s = 128; s > 0; s >>= 1) {
        if (tid < s) sred[tid] = fmaxf(sred[tid], sred[tid + s]);
        __syncthreads();
    }
    const float maxv = fmaxf(sred[0], 1e-20f);
    const float s1 = maxv / 127.f;
    const float inv1 = 127.f / maxv;
    const float s2 = s1 * (1.f / 128.f);
    const float inv2 = 1.f / s2;
    if (tid == 0) g_s2[b] = s2;

    const int jb = b >> 3;
    const int lbase = (b & 7) << 2;
    int isum = 0;
#pragma unroll
    for (int j = 0; j < 8; ++j) {
        float4 v = xr4[tid * 8 + j];
        float vs[4] = {v.x, v.y, v.z, v.w};
        uint32_t u1 = 0, u2 = 0;
#pragma unroll
        for (int e = 0; e < 4; ++e) {
            int q1 = __float2int_rn(vs[e] * inv1);
            float r = fmaf(-s1, (float)q1, vs[e]);
            int q2 = __float2int_rn(r * inv2);
            u1 |= (uint32_t)(q1 & 0xFF) << (8 * e);
            u2 |= (uint32_t)(q2 & 0xFF) << (8 * e);
            isum += (q1 << 7) + q2;
        }
        int k0 = tid * 32 + j * 4;
        int g = k0 >> 6;
        int kin = k0 & 63;
        int cc = (kin >> 2) & 3;
        int u = kin >> 4;
        int idx = (((g << 3) | jb) * 32 + (lbase | cc)) * 4 + u;
        g_xq1[idx] = u1;
        g_xq2[idx] = u2;
    }
    ssum[tid] = isum;
    __syncthreads();
    if (tid < NG) g_xsums[tid * B_DIM + b] = ssum[2 * tid] + ssum[2 * tid + 1];
}

// ---------------- main int8 GEMM + fused last-CTA reduction -----------------
__device__ __forceinline__ uint32_t pack_lo_bytes(uint4 a) {
    return __byte_perm(__byte_perm(a.x, a.y, 0x0040),
                       __byte_perm(a.z, a.w, 0x0040), 0x5410);
}

template <int FMT>
__device__ __forceinline__ uint4 load_w(const uint32_t* __restrict__ w, int row, int gg) {
    if (FMT == 0) {
        return reinterpret_cast<const uint4*>(w)[(size_t)row * 128 + gg];
    } else {
        const uint4* p = reinterpret_cast<const uint4*>(w) + (size_t)row * 512 + gg * 4;
        uint4 r;
        r.x = pack_lo_bytes(p[0]);
        r.y = pack_lo_bytes(p[1]);
        r.z = pack_lo_bytes(p[2]);
        r.w = pack_lo_bytes(p[3]);
        return r;
    }
}

template <int FMT>
__global__ void __launch_bounds__(256, 2) gemm_kernel(
    const uint32_t* __restrict__ wraw,
    const float* __restrict__ scales, const int* __restrict__ zps,
    float* __restrict__ out, const float* __restrict__ bias) {
    if (g_wfmt != FMT) return;
    __shared__ uint32_t lut[256];
    __shared__ float tile2[32][65];
    __shared__ int s_flag;

    const int tid = threadIdx.x;
    const int wid = tid >> 5, lane = tid & 31;
    const int c = lane & 3, sh = c * 8;

    {
        uint32_t v = (uint32_t)tid;
        uint32_t e = 0;
#pragma unroll
        for (int i = 0; i < 4; ++i) {
            int code = (int)((v >> (2 * i)) & 3u) - 2;
            e |= ((uint32_t)code & 0xFFu) << (8 * i);
        }
        lut[tid] = e;
    }
    __syncthreads();   // LUT visible

    const uint4* xq1 = reinterpret_cast<const uint4*>(g_xq1);
    const uint4* xq2 = reinterpret_cast<const uint4*>(g_xq2);
    const int zero = 0;

    int u = (blockIdx.x * NUNITS) / NCTA;
    const int uend = ((blockIdx.x + 1) * NUNITS) / NCTA;
    int seg = 0;

    while (u < uend) {
        const int mt = u >> 7;                       // m-tile
        const int gend = min(uend, (mt + 1) << 7);
        const int g0 = u & 127;
        const int gcnt = gend - u;
        const int R0 = mt * 128 + wid * 16 + (lane >> 2);
        const int R1 = R0 + 8;

        float acc[32];
#pragma unroll
        for (int i = 0; i < 32; ++i) acc[i] = 0.f;

        uint4 W0 = load_w<FMT>(wraw, R0, g0);
        uint4 W1 = load_w<FMT>(wraw, R1, g0);
        float sw0 = scales[(size_t)R0 * NG + g0];
        float sw1 = scales[(size_t)R1 * NG + g0];
        int zp0 = zps[(size_t)R0 * NG + g0];
        int zp1 = zps[(size_t)R1 * NG + g0];

        for (int t = 0; t < gcnt; ++t) {
            const int gg = g0 + t;
            uint4 nW0, nW1;
            float nsw0 = 0.f, nsw1 = 0.f;
            int nzp0 = 2, nzp1 = 2;
            if (t + 1 < gcnt) {
                const int gn = gg + 1;
                nW0 = load_w<FMT>(wraw, R0, gn);
                nW1 = load_w<FMT>(wraw, R1, gn);
                nsw0 = scales[(size_t)R0 * NG + gn];
                nsw1 = scales[(size_t)R1 * NG + gn];
                nzp0 = zps[(size_t)R0 * NG + gn];
                nzp1 = zps[(size_t)R1 * NG + gn];
            }

            uint32_t A00 = lut[(W0.x >> sh) & 0xFF];
            uint32_t A01 = lut[(W1.x >> sh) & 0xFF];
            uint32_t A02 = lut[(W0.y >> sh) & 0xFF];
            uint32_t A03 = lut[(W1.y >> sh) & 0xFF];
            uint32_t A10 = lut[(W0.z >> sh) & 0xFF];
            uint32_t A11 = lut[(W1.z >> sh) & 0xFF];
            uint32_t A12 = lut[(W0.w >> sh) & 0xFF];
            uint32_t A13 = lut[(W1.w >> sh) & 0xFF];

#pragma unroll
            for (int j = 0; j < 8; ++j) {
                uint4 Xp = __ldg(&xq1[(size_t)(gg * 8 + j) * 32 + lane]);
                uint4 Xq = __ldg(&xq2[(size_t)(gg * 8 + j) * 32 + lane]);
                int p10, p11, p12, p13, pa0, pa1, pa2, pa3;
                int p20, p21, p22, p23, pb0, pb1, pb2, pb3;
                mma_s8(p10, p11, p12, p13, A00, A01, A02, A03, Xp.x, Xp.y, zero, zero, zero, zero);
                mma_s8(p20, p21, p22, p23, A00, A01, A02, A03, Xq.x, Xq.y, zero, zero, zero, zero);
                mma_s8(pa0, pa1, pa2, pa3, A10, A11, A12, A13, Xp.z, Xp.w, zero, zero, zero, zero);
                mma_s8(pb0, pb1, pb2, pb3, A10, A11, A12, A13, Xq.z, Xq.w, zero, zero, zero, zero);
                int t0 = ((p10 + pa0) << 7) + (p20 + pb0) + 0x4B400000;
                int t1 = ((p11 + pa1) << 7) + (p21 + pb1) + 0x4B400000;
                int t2 = ((p12 + pa2) << 7) + (p22 + pb2) + 0x4B400000;
                int t3 = ((p13 + pa3) << 7) + (p23 + pb3) + 0x4B400000;
                acc[j * 4 + 0] = fmaf(sw0, __int_as_float(t0) - 12582912.f, acc[j * 4 + 0]);
                acc[j * 4 + 1] = fmaf(sw0, __int_as_float(t1) - 12582912.f, acc[j * 4 + 1]);
                acc[j * 4 + 2] = fmaf(sw1, __int_as_float(t2) - 12582912.f, acc[j * 4 + 2]);
                acc[j * 4 + 3] = fmaf(sw1, __int_as_float(t3) - 12582912.f, acc[j * 4 + 3]);
            }

            if ((zp0 != 2) || (zp1 != 2)) {
                float t0 = sw0 * (float)(2 - zp0);
                float t1 = sw1 * (float)(2 - zp1);
#pragma unroll
                for (int j = 0; j < 8; ++j) {
                    int col = 8 * j + 2 * c;
                    float xs0 = (float)g_xsums[gg * B_DIM + col];
                    float xs1 = (float)g_xsums[gg * B_DIM + col + 1];
                    acc[j * 4 + 0] += t0 * xs0;
                    acc[j * 4 + 1] += t0 * xs1;
                    acc[j * 4 + 2] += t1 * xs0;
                    acc[j * 4 + 3] += t1 * xs1;
                }
            }

            W0 = nW0; W1 = nW1;
            sw0 = nsw0; sw1 = nsw1; zp0 = nzp0; zp1 = nzp1;
        }

        // flush this segment's partial
        float* part = g_part2 + (size_t)(blockIdx.x * 2 + seg) * (128 * B_DIM);
        const int r0 = wid * 16 + (lane >> 2);
#pragma unroll
        for (int j = 0; j < 8; ++j) {
            int col = 8 * j + 2 * c;
            *reinterpret_cast<float2*>(part + (size_t)r0 * B_DIM + col) =
                make_float2(acc[j * 4 + 0], acc[j * 4 + 1]);
            *reinterpret_cast<float2*>(part + (size_t)(r0 + 8) * B_DIM + col) =
                make_float2(acc[j * 4 + 2], acc[j * 4 + 3]);
        }

        // ---- arrive; last CTA for this m-tile reduces it ----
        const int ilo = (37 * mt) >> 3;
        int ihi = ((37 * mt + 44) >> 3) - 1;
        if (ihi > NCTA - 1) ihi = NCTA - 1;

        __threadfence();
        __syncthreads();
        if (tid == 0) {
            int old = atomicAdd(&g_cnt[mt], 1);
            s_flag = (old == (ihi - ilo)) ? 1 : 0;
        }
        __syncthreads();

        if (s_flag) {
            for (int rc = 0; rc < 4; ++rc) {
                const int rbase = mt * 128 + rc * 32;
#pragma unroll
                for (int it = 0; it < 2; ++it) {
                    int idx = tid + it * 256;     // 32 rows x 16 float4-chunks
                    int mi = idx >> 4, bq = idx & 15;
                    int r128 = rc * 32 + mi;
                    float4 v = make_float4(0.f, 0.f, 0.f, 0.f);
                    for (int i = ilo; i <= ihi; ++i) {
                        int stt = (i * NUNITS) / NCTA;
                        int s = mt - (stt >> 7);
                        const float4* p = reinterpret_cast<const float4*>(
                            g_part2 + (size_t)(i * 2 + s) * (128 * B_DIM) + r128 * B_DIM + bq * 4);
                        float4 a = *p;
                        v.x += a.x; v.y += a.y; v.z += a.z; v.w += a.w;
                    }
                    tile2[mi][bq * 4 + 0] = v.x;
                    tile2[mi][bq * 4 + 1] = v.y;
                    tile2[mi][bq * 4 + 2] = v.z;
                    tile2[mi][bq * 4 + 3] = v.w;
                }
                __syncthreads();
#pragma unroll
                for (int it = 0; it < 8; ++it) {
                    int idx = tid + it * 256;
                    int b = idx >> 5, mi = idx & 31;
                    out[(size_t)b * OUT_DIM + rbase + mi] =
                        fmaf(g_s2[b], tile2[mi][b], bias[rbase + mi]);
                }
                __syncthreads();
            }
            if (tid == 0) g_cnt[mt] = 0;   // reset for next replay (deterministic)
        }

        seg++;
        u = gend;
    }
}

extern "C" void kernel_launch(void* const* d_in, const int* in_sizes, int n_in,
                              void* d_out, int out_size) {
    const float* x = (const float*)d_in[0];
    const uint32_t* wraw = (const uint32_t*)d_in[1];
    const float* scales = (const float*)d_in[2];
    const int* zps = (const int*)d_in[3];
    const float* bias = (const float*)d_in[4];
    float* out = (float*)d_out;
    (void)in_sizes; (void)n_in; (void)out_size;

    prep_kernel<<<B_DIM, 256>>>(x, wraw);
    gemm_kernel<0><<<NCTA, 256>>>(wraw, scales, zps, out, bias);
    gemm_kernel<1><<<NCTA, 256>>>(wraw, scales, zps, out, bias);
}

// round 16
// speedup vs baseline: 1.0799x; 1.0799x over previous
#include <cuda_runtime.h>
#include <cuda_bf16.h>
#include <cstdint>

#define B_DIM   64
#define IN_DIM  8192
#define OUT_DIM 8192
#define G_DIM   64
#define NG      (IN_DIM / G_DIM)      // 128 groups per row
#define NCTA    296                   // 148 SMs x 2 CTAs: one perfect wave
#define NUNITS  8192                  // 64 m-tiles x 128 groups

// permuted x planes: [g][j(8)][lane(32)][16B]
__device__ __align__(16) uint32_t g_xq1[NG * 8 * 32 * 4];
__device__ __align__(16) uint32_t g_xq2[NG * 8 * 32 * 4];
__device__ int   g_xsums[NG * B_DIM];
__device__ float g_s2[B_DIM];
__device__ float g_hmax[B_DIM * 2];
// per-CTA partials: [cta][slot(2)][row128][b64]
__device__ __align__(16) float g_part2[NCTA * 2 * 128 * B_DIM];
__device__ int g_wfmt;   // 0 = packed u8, 1 = widened i32

__device__ __forceinline__ void mma_s8(int& d0, int& d1, int& d2, int& d3,
                                       uint32_t a0, uint32_t a1, uint32_t a2, uint32_t a3,
                                       uint32_t b0, uint32_t b1,
                                       int c0, int c1, int c2, int c3) {
    asm("mma.sync.aligned.m16n8k32.row.col.s32.s8.s8.s32 "
        "{%0,%1,%2,%3},{%4,%5,%6,%7},{%8,%9},{%10,%11,%12,%13};"
        : "=r"(d0), "=r"(d1), "=r"(d2), "=r"(d3)
        : "r"(a0), "r"(a1), "r"(a2), "r"(a3), "r"(b0), "r"(b1),
          "r"(c0), "r"(c1), "r"(c2), "r"(c3));
}

// ---------------- pass 1: half-row |x| max + fused format detect ------------
__global__ void __launch_bounds__(256) max_kernel(const float* __restrict__ x,
                                                  const uint32_t* __restrict__ w) {
    const int blk = blockIdx.x;            // 128 blocks = 64 rows x 2 halves
    const int b = blk >> 1, q = blk & 1;
    const int tid = threadIdx.x;
    __shared__ float sred[256];

    if (blk == 0) {
        uint32_t acc_w = 0;
#pragma unroll
        for (int i = 0; i < 8; ++i)
            acc_w |= w[(size_t)(tid * 8 + i) * 2048] & 0xFFFFFF00u;
        unsigned any = __syncthreads_or(acc_w != 0u);
        if (tid == 0) g_wfmt = any ? 0 : 1;
    }

    const float4* xr4 = reinterpret_cast<const float4*>(x + (size_t)b * IN_DIM) + q * 1024;
    float m = 0.f;
#pragma unroll
    for (int it = 0; it < 4; ++it) {
        float4 v = xr4[tid + it * 256];
        m = fmaxf(m, fmaxf(fmaxf(fabsf(v.x), fabsf(v.y)), fmaxf(fabsf(v.z), fabsf(v.w))));
    }
    sred[tid] = m;
    __syncthreads();
    for (int s = 128; s > 0; s >>= 1) {
        if (tid < s) sred[tid] = fmaxf(sred[tid], sred[tid + s]);
        __syncthreads();
    }
    if (tid == 0) g_hmax[blk] = sred[0];
}

// ---------------- pass 2: 2-plane int8 quantization (2 blocks per row) ------
__global__ void __launch_bounds__(256) quant_kernel(const float* __restrict__ x) {
    const int blk = blockIdx.x;            // 128 blocks = 64 rows x 2 halves
    const int b = blk >> 1, q = blk & 1;
    const int tid = threadIdx.x;
    __shared__ int ssum[256];

    const float maxv = fmaxf(fmaxf(g_hmax[b * 2], g_hmax[b * 2 + 1]), 1e-20f);
    const float s1 = maxv / 127.f;
    const float inv1 = 127.f / maxv;
    const float s2 = s1 * (1.f / 128.f);
    const float inv2 = 1.f / s2;
    if (q == 0 && tid == 0) g_s2[b] = s2;

    const float4* xr4 = reinterpret_cast<const float4*>(x + (size_t)b * IN_DIM) + q * 1024;
    const int jb = b >> 3;
    const int lbase = (b & 7) << 2;
    int isum = 0;
#pragma unroll
    for (int j = 0; j < 4; ++j) {          // thread owns 16 consecutive k
        float4 v = xr4[tid * 4 + j];
        float vs[4] = {v.x, v.y, v.z, v.w};
        uint32_t u1 = 0, u2 = 0;
#pragma unroll
        for (int e = 0; e < 4; ++e) {
            int q1 = __float2int_rn(vs[e] * inv1);
            float r = fmaf(-s1, (float)q1, vs[e]);
            int q2 = __float2int_rn(r * inv2);
            u1 |= (uint32_t)(q1 & 0xFF) << (8 * e);
            u2 |= (uint32_t)(q2 & 0xFF) << (8 * e);
            isum += (q1 << 7) + q2;
        }
        int k0 = q * 4096 + tid * 16 + j * 4;
        int g = k0 >> 6;
        int kin = k0 & 63;
        int cc = (kin >> 2) & 3;
        int u = kin >> 4;
        int idx = (((g << 3) | jb) * 32 + (lbase | cc)) * 4 + u;
        g_xq1[idx] = u1;
        g_xq2[idx] = u2;
    }
    ssum[tid] = isum;
    __syncthreads();
    if (tid < 64) {                        // 64 groups per half-row
        int gg = q * 64 + tid;
        g_xsums[gg * B_DIM + b] =
            ssum[4 * tid] + ssum[4 * tid + 1] + ssum[4 * tid + 2] + ssum[4 * tid + 3];
    }
}

// ---------------- main int8 GEMM: 296 balanced CTAs, one wave ---------------
__device__ __forceinline__ uint32_t pack_lo_bytes(uint4 a) {
    return __byte_perm(__byte_perm(a.x, a.y, 0x0040),
                       __byte_perm(a.z, a.w, 0x0040), 0x5410);
}

template <int FMT>
__device__ __forceinline__ uint4 load_w(const uint32_t* __restrict__ w, int row, int gg) {
    if (FMT == 0) {
        return reinterpret_cast<const uint4*>(w)[(size_t)row * 128 + gg];
    } else {
        const uint4* p = reinterpret_cast<const uint4*>(w) + (size_t)row * 512 + gg * 4;
        uint4 r;
        r.x = pack_lo_bytes(p[0]);
        r.y = pack_lo_bytes(p[1]);
        r.z = pack_lo_bytes(p[2]);
        r.w = pack_lo_bytes(p[3]);
        return r;
    }
}

template <int FMT>
__global__ void __launch_bounds__(256, 2) gemm_kernel(
    const uint32_t* __restrict__ wraw,
    const float* __restrict__ scales, const int* __restrict__ zps) {
    if (g_wfmt != FMT) return;
    __shared__ uint32_t lut[256];

    const int tid = threadIdx.x;
    const int wid = tid >> 5, lane = tid & 31;
    const int c = lane & 3, sh = c * 8;

    {
        uint32_t v = (uint32_t)tid;
        uint32_t e = 0;
#pragma unroll
        for (int i = 0; i < 4; ++i) {
            int code = (int)((v >> (2 * i)) & 3u) - 2;
            e |= ((uint32_t)code & 0xFFu) << (8 * i);
        }
        lut[tid] = e;
    }
    __syncthreads();   // LUT visible; the ONLY barrier in this kernel

    const uint4* xq1 = reinterpret_cast<const uint4*>(g_xq1);
    const uint4* xq2 = reinterpret_cast<const uint4*>(g_xq2);
    const int zero = 0;

    int u = (blockIdx.x * NUNITS) / NCTA;
    const int uend = ((blockIdx.x + 1) * NUNITS) / NCTA;
    int seg = 0;

    while (u < uend) {
        const int mt = u >> 7;                       // m-tile
        const int gend = min(uend, (mt + 1) << 7);
        const int g0 = u & 127;
        const int gcnt = gend - u;
        const int R0 = mt * 128 + wid * 16 + (lane >> 2);
        const int R1 = R0 + 8;

        float acc[32];
#pragma unroll
        for (int i = 0; i < 32; ++i) acc[i] = 0.f;

        uint4 W0 = load_w<FMT>(wraw, R0, g0);
        uint4 W1 = load_w<FMT>(wraw, R1, g0);
        float sw0 = scales[(size_t)R0 * NG + g0];
        float sw1 = scales[(size_t)R1 * NG + g0];
        int zp0 = zps[(size_t)R0 * NG + g0];
        int zp1 = zps[(size_t)R1 * NG + g0];

        for (int t = 0; t < gcnt; ++t) {
            const int gg = g0 + t;
            uint4 nW0, nW1;
            float nsw0 = 0.f, nsw1 = 0.f;
            int nzp0 = 2, nzp1 = 2;
            if (t + 1 < gcnt) {
                const int gn = gg + 1;
                nW0 = load_w<FMT>(wraw, R0, gn);
                nW1 = load_w<FMT>(wraw, R1, gn);
                nsw0 = scales[(size_t)R0 * NG + gn];
                nsw1 = scales[(size_t)R1 * NG + gn];
                nzp0 = zps[(size_t)R0 * NG + gn];
                nzp1 = zps[(size_t)R1 * NG + gn];
            }

            uint32_t A00 = lut[(W0.x >> sh) & 0xFF];
            uint32_t A01 = lut[(W1.x >> sh) & 0xFF];
            uint32_t A02 = lut[(W0.y >> sh) & 0xFF];
            uint32_t A03 = lut[(W1.y >> sh) & 0xFF];
            uint32_t A10 = lut[(W0.z >> sh) & 0xFF];
            uint32_t A11 = lut[(W1.z >> sh) & 0xFF];
            uint32_t A12 = lut[(W0.w >> sh) & 0xFF];
            uint32_t A13 = lut[(W1.w >> sh) & 0xFF];

#pragma unroll
            for (int j = 0; j < 8; ++j) {
                uint4 Xp = __ldg(&xq1[(size_t)(gg * 8 + j) * 32 + lane]);
                uint4 Xq = __ldg(&xq2[(size_t)(gg * 8 + j) * 32 + lane]);
                // 4 fully independent MMAs (halves merged in int below)
                int p10, p11, p12, p13, pa0, pa1, pa2, pa3;
                int p20, p21, p22, p23, pb0, pb1, pb2, pb3;
                mma_s8(p10, p11, p12, p13, A00, A01, A02, A03, Xp.x, Xp.y, zero, zero, zero, zero);
                mma_s8(p20, p21, p22, p23, A00, A01, A02, A03, Xq.x, Xq.y, zero, zero, zero, zero);
                mma_s8(pa0, pa1, pa2, pa3, A10, A11, A12, A13, Xp.z, Xp.w, zero, zero, zero, zero);
                mma_s8(pb0, pb1, pb2, pb3, A10, A11, A12, A13, Xq.z, Xq.w, zero, zero, zero, zero);
                int t0 = ((p10 + pa0) << 7) + (p20 + pb0) + 0x4B400000;
                int t1 = ((p11 + pa1) << 7) + (p21 + pb1) + 0x4B400000;
                int t2 = ((p12 + pa2) << 7) + (p22 + pb2) + 0x4B400000;
                int t3 = ((p13 + pa3) << 7) + (p23 + pb3) + 0x4B400000;
                acc[j * 4 + 0] = fmaf(sw0, __int_as_float(t0) - 12582912.f, acc[j * 4 + 0]);
                acc[j * 4 + 1] = fmaf(sw0, __int_as_float(t1) - 12582912.f, acc[j * 4 + 1]);
                acc[j * 4 + 2] = fmaf(sw1, __int_as_float(t2) - 12582912.f, acc[j * 4 + 2]);
                acc[j * 4 + 3] = fmaf(sw1, __int_as_float(t3) - 12582912.f, acc[j * 4 + 3]);
            }

            if ((zp0 != 2) || (zp1 != 2)) {
                float t0 = sw0 * (float)(2 - zp0);
                float t1 = sw1 * (float)(2 - zp1);
#pragma unroll
                for (int j = 0; j < 8; ++j) {
                    int col = 8 * j + 2 * c;
                    float xs0 = (float)g_xsums[gg * B_DIM + col];
                    float xs1 = (float)g_xsums[gg * B_DIM + col + 1];
                    acc[j * 4 + 0] += t0 * xs0;
                    acc[j * 4 + 1] += t0 * xs1;
                    acc[j * 4 + 2] += t1 * xs0;
                    acc[j * 4 + 3] += t1 * xs1;
                }
            }

            W0 = nW0; W1 = nW1;
            sw0 = nsw0; sw1 = nsw1; zp0 = nzp0; zp1 = nzp1;
        }

        // flush this segment's partial
        float* part = g_part2 + (size_t)(blockIdx.x * 2 + seg) * (128 * B_DIM);
        const int r0 = wid * 16 + (lane >> 2);
#pragma unroll
        for (int j = 0; j < 8; ++j) {
            int col = 8 * j + 2 * c;
            *reinterpret_cast<float2*>(part + (size_t)r0 * B_DIM + col) =
                make_float2(acc[j * 4 + 0], acc[j * 4 + 1]);
            *reinterpret_cast<float2*>(part + (size_t)(r0 + 8) * B_DIM + col) =
                make_float2(acc[j * 4 + 2], acc[j * 4 + 3]);
        }

        seg++;
        u = gend;
    }
}

// ---------------- reduce: float4 gather per m-tile, s2[b], bias, transpose --
__global__ void __launch_bounds__(256) reduce_kernel(float* __restrict__ out,
                                                     const float* __restrict__ bias) {
    __shared__ float tile[32][65];
    const int rbase = blockIdx.x * 32;        // 32 rows, all within one m-tile
    const int mt = rbase >> 7;
    const int ilo = (37 * mt) >> 3;           // first CTA overlapping m-tile mt
    int ihi = ((37 * mt + 44) >> 3) - 1;      // last CTA overlapping m-tile mt
    if (ihi > NCTA - 1) ihi = NCTA - 1;
    const int tid = threadIdx.x;

    // gather phase: float4 chunks (16 per 64-float row), 2 chunks per thread
#pragma unroll
    for (int it = 0; it < 2; ++it) {
        int idx = tid + it * 256;             // 0..511 = 32 rows x 16 chunks
        int mi = idx >> 4, bq = idx & 15;
        int r128 = (rbase + mi) & 127;
        float4 v = make_float4(0.f, 0.f, 0.f, 0.f);
        for (int i = ilo; i <= ihi; ++i) {
            int stt = (i * NUNITS) / NCTA;
            int s = mt - (stt >> 7);          // slot 0 or 1 by construction
            const float4* p = reinterpret_cast<const float4*>(
                g_part2 + (size_t)(i * 2 + s) * (128 * B_DIM) + r128 * B_DIM + bq * 4);
            float4 a = __ldg(p);
            v.x += a.x; v.y += a.y; v.z += a.z; v.w += a.w;
        }
        tile[mi][bq * 4 + 0] = v.x;
        tile[mi][bq * 4 + 1] = v.y;
        tile[mi][bq * 4 + 2] = v.z;
        tile[mi][bq * 4 + 3] = v.w;
    }
    __syncthreads();
    // transpose phase: warp = one output row of 32 m (128B coalesced)
#pragma unroll
    for (int it = 0; it < 8; ++it) {
        int idx = tid + it * 256;
        int b = idx >> 5, mi = idx & 31;
        out[(size_t)b * OUT_DIM + rbase + mi] = fmaf(g_s2[b], tile[mi][b], bias[rbase + mi]);
    }
}

extern "C" void kernel_launch(void* const* d_in, const int* in_sizes, int n_in,
                              void* d_out, int out_size) {
    const float* x = (const float*)d_in[0];
    const uint32_t* wraw = (const uint32_t*)d_in[1];
    const float* scales = (const float*)d_in[2];
    const int* zps = (const int*)d_in[3];
    const float* bias = (const float*)d_in[4];
    float* out = (float*)d_out;
    (void)in_sizes; (void)n_in; (void)out_size;

    max_kernel<<<128, 256>>>(x, wraw);
    quant_kernel<<<128, 256>>>(x);
    gemm_kernel<0><<<NCTA, 256>>>(wraw, scales, zps);
    gemm_kernel<1><<<NCTA, 256>>>(wraw, scales, zps);
    reduce_kernel<<<OUT_DIM / 32, 256>>>(out, bias);
}

// round 17
// speedup vs baseline: 1.0849x; 1.0047x over previous
#include <cuda_runtime.h>
#include <cuda_bf16.h>
#include <cstdint>

#define B_DIM   64
#define IN_DIM  8192
#define OUT_DIM 8192
#define G_DIM   64
#define NG      (IN_DIM / G_DIM)      // 128 groups per row
#define NCTA    296                   // 148 SMs x 2 CTAs: one perfect wave
#define NUNITS  8192                  // 64 m-tiles x 128 groups

// permuted x planes: [g][j(8)][lane(32)][16B]
__device__ __align__(16) uint32_t g_xq1[NG * 8 * 32 * 4];
__device__ __align__(16) uint32_t g_xq2[NG * 8 * 32 * 4];
__device__ int   g_xsums[NG * B_DIM];
__device__ float g_s2[B_DIM];
__device__ float g_hmax[B_DIM * 2];
// per-CTA partials: [cta][slot(2)][row128][b64]
__device__ __align__(16) float g_part2[NCTA * 2 * 128 * B_DIM];
__device__ int g_wfmt;   // 0 = packed u8, 1 = widened i32

__device__ __forceinline__ void mma_s8(int& d0, int& d1, int& d2, int& d3,
                                       uint32_t a0, uint32_t a1, uint32_t a2, uint32_t a3,
                                       uint32_t b0, uint32_t b1,
                                       int c0, int c1, int c2, int c3) {
    asm("mma.sync.aligned.m16n8k32.row.col.s32.s8.s8.s32 "
        "{%0,%1,%2,%3},{%4,%5,%6,%7},{%8,%9},{%10,%11,%12,%13};"
        : "=r"(d0), "=r"(d1), "=r"(d2), "=r"(d3)
        : "r"(a0), "r"(a1), "r"(a2), "r"(a3), "r"(b0), "r"(b1),
          "r"(c0), "r"(c1), "r"(c2), "r"(c3));
}

// ---------------- pass 1: half-row |x| max + fused format detect ------------
__global__ void __launch_bounds__(256) max_kernel(const float* __restrict__ x,
                                                  const uint32_t* __restrict__ w) {
    const int blk = blockIdx.x;            // 128 blocks = 64 rows x 2 halves
    const int b = blk >> 1, q = blk & 1;
    const int tid = threadIdx.x;
    __shared__ float sred[256];

    if (blk == 0) {
        uint32_t acc_w = 0;
#pragma unroll
        for (int i = 0; i < 8; ++i)
            acc_w |= w[(size_t)(tid * 8 + i) * 2048] & 0xFFFFFF00u;
        unsigned any = __syncthreads_or(acc_w != 0u);
        if (tid == 0) g_wfmt = any ? 0 : 1;
    }

    const float4* xr4 = reinterpret_cast<const float4*>(x + (size_t)b * IN_DIM) + q * 1024;
    float m = 0.f;
#pragma unroll
    for (int it = 0; it < 4; ++it) {
        float4 v = xr4[tid + it * 256];
        m = fmaxf(m, fmaxf(fmaxf(fabsf(v.x), fabsf(v.y)), fmaxf(fabsf(v.z), fabsf(v.w))));
    }
    sred[tid] = m;
    __syncthreads();
    for (int s = 128; s > 0; s >>= 1) {
        if (tid < s) sred[tid] = fmaxf(sred[tid], sred[tid + s]);
        __syncthreads();
    }
    if (tid == 0) g_hmax[blk] = sred[0];
}

// ---------------- pass 2: 2-plane int8 quantization (2 blocks per row) ------
__global__ void __launch_bounds__(256) quant_kernel(const float* __restrict__ x) {
    const int blk = blockIdx.x;            // 128 blocks = 64 rows x 2 halves
    const int b = blk >> 1, q = blk & 1;
    const int tid = threadIdx.x;
    __shared__ int ssum[256];

    const float maxv = fmaxf(fmaxf(g_hmax[b * 2], g_hmax[b * 2 + 1]), 1e-20f);
    const float s1 = maxv / 127.f;
    const float inv1 = 127.f / maxv;
    const float s2 = s1 * (1.f / 128.f);
    const float inv2 = 1.f / s2;
    if (q == 0 && tid == 0) g_s2[b] = s2;

    const float4* xr4 = reinterpret_cast<const float4*>(x + (size_t)b * IN_DIM) + q * 1024;
    const int jb = b >> 3;
    const int lbase = (b & 7) << 2;
    int isum = 0;
#pragma unroll
    for (int j = 0; j < 4; ++j) {          // thread owns 16 consecutive k
        float4 v = xr4[tid * 4 + j];
        float vs[4] = {v.x, v.y, v.z, v.w};
        uint32_t u1 = 0, u2 = 0;
#pragma unroll
        for (int e = 0; e < 4; ++e) {
            int q1 = __float2int_rn(vs[e] * inv1);
            float r = fmaf(-s1, (float)q1, vs[e]);
            int q2 = __float2int_rn(r * inv2);
            u1 |= (uint32_t)(q1 & 0xFF) << (8 * e);
            u2 |= (uint32_t)(q2 & 0xFF) << (8 * e);
            isum += (q1 << 7) + q2;
        }
        int k0 = q * 4096 + tid * 16 + j * 4;
        int g = k0 >> 6;
        int kin = k0 & 63;
        int cc = (kin >> 2) & 3;
        int u = kin >> 4;
        int idx = (((g << 3) | jb) * 32 + (lbase | cc)) * 4 + u;
        g_xq1[idx] = u1;
        g_xq2[idx] = u2;
    }
    ssum[tid] = isum;
    __syncthreads();
    if (tid < 64) {                        // 64 groups per half-row
        int gg = q * 64 + tid;
        g_xsums[gg * B_DIM + b] =
            ssum[4 * tid] + ssum[4 * tid + 1] + ssum[4 * tid + 2] + ssum[4 * tid + 3];
    }
}

// ---------------- main int8 GEMM: 296 balanced CTAs, one wave ---------------
__device__ __forceinline__ uint32_t pack_lo_bytes(uint4 a) {
    return __byte_perm(__byte_perm(a.x, a.y, 0x0040),
                       __byte_perm(a.z, a.w, 0x0040), 0x5410);
}

template <int FMT>
__device__ __forceinline__ uint4 load_w(const uint32_t* __restrict__ w, int row, int gg) {
    if (FMT == 0) {
        return reinterpret_cast<const uint4*>(w)[(size_t)row * 128 + gg];
    } else {
        const uint4* p = reinterpret_cast<const uint4*>(w) + (size_t)row * 512 + gg * 4;
        uint4 r;
        r.x = pack_lo_bytes(p[0]);
        r.y = pack_lo_bytes(p[1]);
        r.z = pack_lo_bytes(p[2]);
        r.w = pack_lo_bytes(p[3]);
        return r;
    }
}

template <int FMT>
__global__ void __launch_bounds__(256, 2) gemm_kernel(
    const uint32_t* __restrict__ wraw,
    const float* __restrict__ scales, const int* __restrict__ zps) {
    if (g_wfmt != FMT) return;
    __shared__ uint32_t lut[256];

    const int tid = threadIdx.x;
    const int wid = tid >> 5, lane = tid & 31;
    const int c = lane & 3, sh = c * 8;

    {
        uint32_t v = (uint32_t)tid;
        uint32_t e = 0;
#pragma unroll
        for (int i = 0; i < 4; ++i) {
            int code = (int)((v >> (2 * i)) & 3u) - 2;
            e |= ((uint32_t)code & 0xFFu) << (8 * i);
        }
        lut[tid] = e;
    }
    __syncthreads();   // LUT visible; the ONLY barrier in this kernel

    const uint4* xq1 = reinterpret_cast<const uint4*>(g_xq1);
    const uint4* xq2 = reinterpret_cast<const uint4*>(g_xq2);
    const int zero = 0;

    int u = (blockIdx.x * NUNITS) / NCTA;
    const int uend = ((blockIdx.x + 1) * NUNITS) / NCTA;
    int seg = 0;

    while (u < uend) {
        const int mt = u >> 7;                       // m-tile
        const int gend = min(uend, (mt + 1) << 7);
        const int g0 = u & 127;
        const int gcnt = gend - u;
        const int R0 = mt * 128 + wid * 16 + (lane >> 2);
        const int R1 = R0 + 8;

        float acc[32];
#pragma unroll
        for (int i = 0; i < 32; ++i) acc[i] = 0.f;

        uint4 W0 = load_w<FMT>(wraw, R0, g0);
        uint4 W1 = load_w<FMT>(wraw, R1, g0);
        float sw0 = scales[(size_t)R0 * NG + g0];
        float sw1 = scales[(size_t)R1 * NG + g0];
        int zp0 = zps[(size_t)R0 * NG + g0];
        int zp1 = zps[(size_t)R1 * NG + g0];

        for (int t = 0; t < gcnt; ++t) {
            const int gg = g0 + t;
            uint4 nW0, nW1;
            float nsw0 = 0.f, nsw1 = 0.f;
            int nzp0 = 2, nzp1 = 2;
            if (t + 1 < gcnt) {
                const int gn = gg + 1;
                nW0 = load_w<FMT>(wraw, R0, gn);
                nW1 = load_w<FMT>(wraw, R1, gn);
                nsw0 = scales[(size_t)R0 * NG + gn];
                nsw1 = scales[(size_t)R1 * NG + gn];
                nzp0 = zps[(size_t)R0 * NG + gn];
                nzp1 = zps[(size_t)R1 * NG + gn];
            }

            uint32_t A00 = lut[(W0.x >> sh) & 0xFF];
            uint32_t A01 = lut[(W1.x >> sh) & 0xFF];
            uint32_t A02 = lut[(W0.y >> sh) & 0xFF];
            uint32_t A03 = lut[(W1.y >> sh) & 0xFF];
            uint32_t A10 = lut[(W0.z >> sh) & 0xFF];
            uint32_t A11 = lut[(W1.z >> sh) & 0xFF];
            uint32_t A12 = lut[(W0.w >> sh) & 0xFF];
            uint32_t A13 = lut[(W1.w >> sh) & 0xFF];

#pragma unroll
            for (int j = 0; j < 8; ++j) {
                uint4 Xp = __ldg(&xq1[(size_t)(gg * 8 + j) * 32 + lane]);
                uint4 Xq = __ldg(&xq2[(size_t)(gg * 8 + j) * 32 + lane]);
                // 4 fully independent MMAs (halves merged in int below)
                int p10, p11, p12, p13, pa0, pa1, pa2, pa3;
                int p20, p21, p22, p23, pb0, pb1, pb2, pb3;
                mma_s8(p10, p11, p12, p13, A00, A01, A02, A03, Xp.x, Xp.y, zero, zero, zero, zero);
                mma_s8(p20, p21, p22, p23, A00, A01, A02, A03, Xq.x, Xq.y, zero, zero, zero, zero);
                mma_s8(pa0, pa1, pa2, pa3, A10, A11, A12, A13, Xp.z, Xp.w, zero, zero, zero, zero);
                mma_s8(pb0, pb1, pb2, pb3, A10, A11, A12, A13, Xq.z, Xq.w, zero, zero, zero, zero);
                int t0 = ((p10 + pa0) << 7) + (p20 + pb0) + 0x4B400000;
                int t1 = ((p11 + pa1) << 7) + (p21 + pb1) + 0x4B400000;
                int t2 = ((p12 + pa2) << 7) + (p22 + pb2) + 0x4B400000;
                int t3 = ((p13 + pa3) << 7) + (p23 + pb3) + 0x4B400000;
                acc[j * 4 + 0] = fmaf(sw0, __int_as_float(t0) - 12582912.f, acc[j * 4 + 0]);
                acc[j * 4 + 1] = fmaf(sw0, __int_as_float(t1) - 12582912.f, acc[j * 4 + 1]);
                acc[j * 4 + 2] = fmaf(sw1, __int_as_float(t2) - 12582912.f, acc[j * 4 + 2]);
                acc[j * 4 + 3] = fmaf(sw1, __int_as_float(t3) - 12582912.f, acc[j * 4 + 3]);
            }

            if ((zp0 != 2) || (zp1 != 2)) {
                float t0 = sw0 * (float)(2 - zp0);
                float t1 = sw1 * (float)(2 - zp1);
#pragma unroll
                for (int j = 0; j < 8; ++j) {
                    int col = 8 * j + 2 * c;
                    float xs0 = (float)g_xsums[gg * B_DIM + col];
                    float xs1 = (float)g_xsums[gg * B_DIM + col + 1];
                    acc[j * 4 + 0] += t0 * xs0;
                    acc[j * 4 + 1] += t0 * xs1;
                    acc[j * 4 + 2] += t1 * xs0;
                    acc[j * 4 + 3] += t1 * xs1;
                }
            }

            W0 = nW0; W1 = nW1;
            sw0 = nsw0; sw1 = nsw1; zp0 = nzp0; zp1 = nzp1;
        }

        // flush this segment's partial
        float* part = g_part2 + (size_t)(blockIdx.x * 2 + seg) * (128 * B_DIM);
        const int r0 = wid * 16 + (lane >> 2);
#pragma unroll
        for (int j = 0; j < 8; ++j) {
            int col = 8 * j + 2 * c;
            *reinterpret_cast<float2*>(part + (size_t)r0 * B_DIM + col) =
                make_float2(acc[j * 4 + 0], acc[j * 4 + 1]);
            *reinterpret_cast<float2*>(part + (size_t)(r0 + 8) * B_DIM + col) =
                make_float2(acc[j * 4 + 2], acc[j * 4 + 3]);
        }

        seg++;
        u = gend;
    }
}

// ---------------- reduce: 512 blocks, float4 gather, s2[b], bias, transpose -
__global__ void __launch_bounds__(256) reduce_kernel(float* __restrict__ out,
                                                     const float* __restrict__ bias) {
    __shared__ float tile[16][65];
    const int rbase = blockIdx.x * 16;        // 16 rows, all within one m-tile
    const int mt = rbase >> 7;
    const int ilo = (37 * mt) >> 3;           // first CTA overlapping m-tile mt
    int ihi = ((37 * mt + 44) >> 3) - 1;      // last CTA overlapping m-tile mt
    if (ihi > NCTA - 1) ihi = NCTA - 1;
    const int tid = threadIdx.x;

    // gather phase: one float4 chunk per thread (16 rows x 16 chunks = 256)
    {
        int mi = tid >> 4, bq = tid & 15;
        int r128 = (rbase + mi) & 127;
        float4 v = make_float4(0.f, 0.f, 0.f, 0.f);
        for (int i = ilo; i <= ihi; ++i) {
            int stt = (i * NUNITS) / NCTA;
            int s = mt - (stt >> 7);          // slot 0 or 1 by construction
            const float4* p = reinterpret_cast<const float4*>(
                g_part2 + (size_t)(i * 2 + s) * (128 * B_DIM) + r128 * B_DIM + bq * 4);
            float4 a = __ldg(p);
            v.x += a.x; v.y += a.y; v.z += a.z; v.w += a.w;
        }
        tile[mi][bq * 4 + 0] = v.x;
        tile[mi][bq * 4 + 1] = v.y;
        tile[mi][bq * 4 + 2] = v.z;
        tile[mi][bq * 4 + 3] = v.w;
    }
    __syncthreads();
    // transpose phase: 16 m-values per b, 64B-contiguous per 16 lanes
#pragma unroll
    for (int it = 0; it < 4; ++it) {
        int idx = tid + it * 256;
        int b = idx >> 4, mi = idx & 15;
        out[(size_t)b * OUT_DIM + rbase + mi] = fmaf(g_s2[b], tile[mi][b], bias[rbase + mi]);
    }
}

extern "C" void kernel_launch(void* const* d_in, const int* in_sizes, int n_in,
                              void* d_out, int out_size) {
    const float* x = (const float*)d_in[0];
    const uint32_t* wraw = (const uint32_t*)d_in[1];
    const float* scales = (const float*)d_in[2];
    const int* zps = (const int*)d_in[3];
    const float* bias = (const float*)d_in[4];
    float* out = (float*)d_out;
    (void)in_sizes; (void)n_in; (void)out_size;

    max_kernel<<<128, 256>>>(x, wraw);
    quant_kernel<<<128, 256>>>(x);
    gemm_kernel<0><<<NCTA, 256>>>(wraw, scales, zps);
    gemm_kernel<1><<<NCTA, 256>>>(wraw, scales, zps);
    reduce_kernel<<<OUT_DIM / 16, 256>>>(out, bias);
}